// round 3
// baseline (speedup 1.0000x reference)
#include <cuda_runtime.h>
#include <cstdint>

typedef unsigned int u32;
typedef unsigned long long u64;

#define NB 32
#define NA 49056
#define NFG 7
#define TOPK 200
#define DETS 200
#define NMSTHR 0.45f
#define LOWSC 0.01f

#define K2T 512
#define NCH 96            // 96*512 = 49152 padded slots
#define NPAD 49152
#define N4 (NA/4)         // 12264 uint4 loads

// ---------------- scratch ----------------------------------------------------
__device__ float g_fg[(size_t)NB*NFG*NA];     // fg scores, class-major
__device__ float g_ks[NB*NFG*TOPK];           // kept scores (sorted desc)
__device__ int   g_ka[NB*NFG*TOPK];           // kept anchors
__device__ float4 g_kb[NB*NFG*TOPK];          // kept clipped boxes (unoffset)
__device__ int   g_kc[NB*NFG];                // kept counts

// ---------------- K1: softmax only ------------------------------------------
__global__ void k1_softmax(const float* __restrict__ logits)
{
    int idx = blockIdx.x*blockDim.x + threadIdx.x;
    if (idx >= NB*NA) return;
    int b = idx / NA;
    int a = idx - b*NA;

    float4 l0 = ((const float4*)logits)[idx*2+0];
    float4 l1 = ((const float4*)logits)[idx*2+1];
    float e[8] = {l0.x,l0.y,l0.z,l0.w,l1.x,l1.y,l1.z,l1.w};
    float mx = e[0];
#pragma unroll
    for (int i=1;i<8;i++) mx = fmaxf(mx,e[i]);
    float s = 0.f;
#pragma unroll
    for (int i=0;i<8;i++){ e[i] = expf(e[i]-mx); s += e[i]; }
#pragma unroll
    for (int c=0;c<7;c++)
        g_fg[((size_t)b*NFG + c)*NA + a] = e[c+1]/s;
}

// ---------------- K2: per-(b,c) top-200 + sort + class NMS -------------------
__global__ __launch_bounds__(K2T) void k2_select_nms(const float* __restrict__ deltas,
                                                     const float* __restrict__ dboxg)
{
    extern __shared__ u32 sv[];               // [NPAD] score bits

    __shared__ u32 shw[16];
    __shared__ u32 shtot;
    __shared__ int sh_pos, sh_ec, sh_pos2;
    __shared__ u32 cs[TOPK];                  // selected score bits
    __shared__ int ca[TOPK];                  // selected anchors
    __shared__ u32 eqA[256];
    __shared__ u64 skeys[256];
    __shared__ float4 rbox[TOPK];             // raw clipped boxes
    __shared__ float sx0[TOPK], sy0[TOPK], sx1[TOPK], sy1[TOPK], sar[TOPK];
    __shared__ u32 M[TOPK*7];
    __shared__ u32 skeep[7];
    __shared__ int warpcnt[8], warpbase[8], sh_tot;

    int bc = blockIdx.x;
    int b  = bc / NFG;
    int c  = bc - b*NFG;
    int tid = threadIdx.x;

    // ---- load class slice to smem (vectorized) ----
    {
        const uint4* src = (const uint4*)(reinterpret_cast<const u32*>(g_fg) + (size_t)bc*NA);
        uint4* dst = (uint4*)sv;
#pragma unroll
        for (int k=0;k<24;k++){
            int i4 = tid + (k<<9);
            if (i4 < N4) dst[i4] = src[i4];
        }
        for (int i = tid; i < NPAD-NA; i += K2T) sv[NA+i] = 0u;
    }
    __syncthreads();

    // ---- block count(>= piv) helper ----
    auto bcount = [&](u32 piv)->int{
        u32 cc = 0;
#pragma unroll
        for (int k=0;k<NCH;k++) cc += (sv[tid + (k<<9)] >= piv) ? 1u : 0u;
        cc = __reduce_add_sync(0xffffffffu, cc);
        __syncthreads();
        if ((tid&31)==0) shw[tid>>5] = cc;
        __syncthreads();
        if (tid==0){ u32 t=0; for (int i=0;i<16;i++) t += shw[i]; shtot = t; }
        __syncthreads();
        return (int)shtot;
    };

    // ---- threshold search (interpolation + bisection, early-exit at ==200) ----
    u32 lo = 1u, hi = 0x3F800001u;
    int clo = NA, chi = 0;
    u32 selT = 0; bool found = false;
    for (int it=0; it<70 && hi-lo>1u; ++it){
        u32 mid;
        if (it & 1){
            mid = lo + ((hi - lo) >> 1);
        } else {
            float fr = (float)(clo - TOPK) / (float)((clo - chi) > 0 ? (clo - chi) : 1);
            if (fr < 0.f) fr = 0.f; if (fr > 1.f) fr = 1.f;
            mid = lo + (u32)((float)(hi - lo) * fr);
            if (mid <= lo) mid = lo + 1;
            if (mid >= hi) mid = hi - 1;
        }
        int cm = bcount(mid);
        if (cm == TOPK){ selT = mid; found = true; break; }
        if (cm > TOPK){ lo = mid; clo = cm; }
        else          { hi = mid; chi = cm; }
    }

    // ---- emission of exactly 200 candidates ----
    if (tid==0){ sh_pos = 0; sh_ec = 0; sh_pos2 = 0; }
    __syncthreads();

    if (found){
#pragma unroll
        for (int k=0;k<NCH;k++){
            int a = tid + (k<<9);
            u32 v = sv[a];
            if (v >= selT){
                int p = atomicAdd(&sh_pos, 1);
                cs[p] = v; ca[p] = a;
            }
        }
        __syncthreads();
    } else {
        u32 P = lo;
        int cg = chi;                    // count strictly greater
        int krem = TOPK - cg;            // from equals, smallest anchors
#pragma unroll
        for (int k=0;k<NCH;k++){
            int a = tid + (k<<9);
            u32 v = sv[a];
            if (v > P){
                int p = atomicAdd(&sh_pos, 1);
                cs[p] = v; ca[p] = a;
            } else if (v == P && a < NA){
                int e = atomicAdd(&sh_ec, 1);
                if (e < 256) eqA[e] = (u32)a;
            }
        }
        __syncthreads();
        int ec = sh_ec;
        if (ec <= 256){
            for (int i = tid; i < 256; i += K2T) if (i >= ec) eqA[i] = 0xFFFFFFFFu;
            __syncthreads();
            for (int kk=2; kk<=256; kk<<=1){
                for (int j=kk>>1; j>0; j>>=1){
                    for (int i=tid; i<256; i+=K2T){
                        int ix = i ^ j;
                        if (ix > i){
                            u32 a0=eqA[i], a1=eqA[ix];
                            bool up = ((i & kk) == 0);
                            if ((a0 > a1) == up){ eqA[i]=a1; eqA[ix]=a0; }
                        }
                    }
                    __syncthreads();
                }
            }
            if (tid < krem){ cs[cg+tid] = P; ca[cg+tid] = (int)eqA[tid]; }
            __syncthreads();
        } else {
            // rare: binary search on anchor among equals
            int alo = 0, ahi = NA;        // cnt(a<alo)<krem, cnt(a<ahi)>=krem
            while (ahi - alo > 1){
                int amid = alo + ((ahi - alo) >> 1);
                u32 cc = 0;
#pragma unroll
                for (int k=0;k<NCH;k++){
                    int a = tid + (k<<9);
                    cc += (sv[a] == P && a < amid) ? 1u : 0u;
                }
                cc = __reduce_add_sync(0xffffffffu, cc);
                __syncthreads();
                if ((tid&31)==0) shw[tid>>5] = cc;
                __syncthreads();
                if (tid==0){ u32 t=0; for (int i=0;i<16;i++) t += shw[i]; shtot = t; }
                __syncthreads();
                if ((int)shtot >= krem) ahi = amid; else alo = amid;
            }
#pragma unroll
            for (int k=0;k<NCH;k++){
                int a = tid + (k<<9);
                if (sv[a] == P && a < ahi){
                    int p = atomicAdd(&sh_pos2, 1);
                    cs[cg+p] = P; ca[cg+p] = a;
                }
            }
            __syncthreads();
        }
    }

    // ---- sort 200 candidates desc by (score, anchor asc) via bitonic-256 ----
    for (int i = tid; i < 256; i += K2T){
        u64 nk = ~0ull;
        if (i < TOPK)
            nk = ~(((u64)cs[i] << 32) | (u64)(0xFFFFFFFFu - (u32)ca[i]));
        skeys[i] = nk;
    }
    __syncthreads();
    for (int kk=2; kk<=256; kk<<=1){
        for (int j=kk>>1; j>0; j>>=1){
            for (int i=tid; i<256; i+=K2T){
                int ix = i ^ j;
                if (ix > i){
                    u64 a0=skeys[i], a1=skeys[ix];
                    bool up = ((i & kk) == 0);
                    if ((a0 > a1) == up){ skeys[i]=a1; skeys[ix]=a0; }
                }
            }
            __syncthreads();
        }
    }
    if (tid < TOPK){
        u64 kk = ~skeys[tid];
        cs[tid] = (u32)(kk >> 32);
        ca[tid] = (int)(0xFFFFFFFFu - (u32)kk);
    }
    // valid prefix: scores > LOW_SCORE
    int m = __syncthreads_count(tid < TOPK && __uint_as_float(cs[tid]) > LOWSC);

    // ---- decode boxes for valid candidates + offset/area ----
    float off = 4.0f * (float)(c + 1);
    for (int i = tid; i < m; i += K2T){
        int a = ca[i];
        float4 d  = ((const float4*)deltas)[(size_t)b*NA + a];
        float4 db = ((const float4*)dboxg)[a];
        float w  = db.z - db.x, h = db.w - db.y;
        float cx = db.x + 0.5f*w, cy = db.y + 0.5f*h;
        float pcx = d.x/10.0f*w + cx;
        float pcy = d.y/10.0f*h + cy;
        float pw  = expf(d.z/5.0f)*w;
        float ph  = expf(d.w/5.0f)*h;
        float4 rb;
        rb.x = fminf(fmaxf(pcx - 0.5f*pw, 0.f), 1.f);
        rb.y = fminf(fmaxf(pcy - 0.5f*ph, 0.f), 1.f);
        rb.z = fminf(fmaxf(pcx + 0.5f*pw, 0.f), 1.f);
        rb.w = fminf(fmaxf(pcy + 0.5f*ph, 0.f), 1.f);
        rbox[i] = rb;
        float x0 = rb.x + off, y0 = rb.y + off;
        float x1 = rb.z + off, y1 = rb.w + off;
        sx0[i]=x0; sy0[i]=y0; sx1[i]=x1; sy1[i]=y1;
        sar[i] = (x1-x0)*(y1-y0);
    }
    for (int i = tid; i < TOPK*7; i += K2T) M[i] = 0u;
    __syncthreads();

    // ---- suppression matrix ----
    int nww = (m + 31) >> 5;
    int ntask = m * nww;
    int lane = tid & 31;
    for (int task = tid; task < ntask; task += K2T){
        int i = task / nww;
        int w = task - i*nww;
        float xi0=sx0[i], yi0=sy0[i], xi1=sx1[i], yi1=sy1[i], ai=sar[i];
        u32 bits = 0;
#pragma unroll
        for (int l=0;l<32;l++){
            int idx = (l + lane) & 31;
            int j = (w<<5) + idx;
            if (j < m && j > i){
                float xl = fmaxf(xi0, sx0[j]);
                float yt = fmaxf(yi0, sy0[j]);
                float xr = fminf(xi1, sx1[j]);
                float yb = fminf(yi1, sy1[j]);
                float inter = fmaxf(xr-xl, 0.f) * fmaxf(yb-yt, 0.f);
                float iou = inter / (ai + sar[j] - inter);
                if (iou > NMSTHR) bits |= (1u << idx);
            }
        }
        M[i*7 + w] = bits;
    }
    __syncthreads();

    // ---- serial greedy walk (thread 0, regs only) ----
    if (tid == 0){
        u32 r0=0,r1=0,r2=0,r3=0,r4=0,r5=0,r6=0;
#define NMSW(W, RW) { int lim = m - (W<<5); if (lim > 32) lim = 32; \
        for (int l=0;l<lim;l++){ \
            if (!((RW >> l) & 1u)){ const u32* row = &M[(((W)<<5)+l)*7]; \
                r0|=row[0]; r1|=row[1]; r2|=row[2]; r3|=row[3]; r4|=row[4]; r5|=row[5]; r6|=row[6]; } } }
        if (m >   0) NMSW(0, r0)
        if (m >  32) NMSW(1, r1)
        if (m >  64) NMSW(2, r2)
        if (m >  96) NMSW(3, r3)
        if (m > 128) NMSW(4, r4)
        if (m > 160) NMSW(5, r5)
        if (m > 192) NMSW(6, r6)
#undef NMSW
        skeep[0]=~r0; skeep[1]=~r1; skeep[2]=~r2; skeep[3]=~r3;
        skeep[4]=~r4; skeep[5]=~r5; skeep[6]=~r6;
    }
    __syncthreads();

    // ---- ordered compaction of kept -> global ----
    u32 bal = 0; bool kept = false;
    int w7 = tid >> 5;
    if (tid < 224){
        kept = (tid < m) && ((skeep[w7] >> lane) & 1u);
        bal = __ballot_sync(0xffffffffu, kept);
        if (lane == 0) warpcnt[w7] = __popc(bal);
    }
    __syncthreads();
    if (tid == 0){
        int s = 0;
        for (int w=0; w<7; w++){ warpbase[w] = s; s += warpcnt[w]; }
        sh_tot = s;
        g_kc[bc] = s;
    }
    __syncthreads();
    if (tid < 224 && kept){
        int pos = warpbase[w7] + __popc(bal & ((1u << lane) - 1u));
        g_ks[bc*TOPK + pos] = __uint_as_float(cs[tid]);
        g_ka[bc*TOPK + pos] = ca[tid];
        g_kb[bc*TOPK + pos] = rbox[tid];
    }
}

// ---------------- K3: per-batch rank-merge of 7 kept lists -------------------
__global__ __launch_bounds__(512) void k3_merge(float* __restrict__ out)
{
    __shared__ u64 sk[NFG*TOPK];
    __shared__ int scnt[NFG];

    int b = blockIdx.x;
    int tid = threadIdx.x;

    // zero output region
    for (int d = tid; d < DETS; d += 512){
        int base = b*DETS + d;
        out[base*4+0]=0.f; out[base*4+1]=0.f; out[base*4+2]=0.f; out[base*4+3]=0.f;
        out[NB*DETS*4 + base] = 0.f;
        out[NB*DETS*5 + base] = 0.f;
    }
    if (tid < NFG) scnt[tid] = g_kc[b*NFG + tid];
    __syncthreads();

    for (int idx = tid; idx < NFG*TOPK; idx += 512){
        int c = idx / TOPK;
        int p = idx - c*TOPK;
        u64 key = 0;
        if (p < scnt[c]){
            float s = g_ks[(b*NFG + c)*TOPK + p];
            int   a = g_ka[(b*NFG + c)*TOPK + p];
            key = ((u64)__float_as_uint(s) << 32)
                | ((u64)(u32)((7 - c) << 16))
                | (u64)(u32)(0xFFFF - a);
        }
        sk[idx] = key;
    }
    __syncthreads();

    for (int idx = tid; idx < NFG*TOPK; idx += 512){
        int c = idx / TOPK;
        int p = idx - c*TOPK;
        if (p < scnt[c]){
            u64 K = sk[idx];
            int r = p;
#pragma unroll
            for (int c2=0; c2<NFG; c2++){
                if (c2 == c) continue;
                const u64* L = sk + c2*TOPK;
                int blo = 0, bhi = scnt[c2];
                while (blo < bhi){
                    int mid = (blo + bhi) >> 1;
                    if (L[mid] > K) blo = mid + 1; else bhi = mid;
                }
                r += blo;
            }
            if (r < DETS){
                float4 bb = g_kb[(b*NFG + c)*TOPK + p];
                float  s  = __uint_as_float((u32)(K >> 32));
                int base = b*DETS + r;
                out[base*4+0]=bb.x; out[base*4+1]=bb.y;
                out[base*4+2]=bb.z; out[base*4+3]=bb.w;
                out[NB*DETS*4 + base] = s;
                out[NB*DETS*5 + base] = (float)(c + 1);
            }
        }
    }
}

// ---------------- launch ----------------------------------------------------
extern "C" void kernel_launch(void* const* d_in, const int* in_sizes, int n_in,
                              void* d_out, int out_size)
{
    const float* logits = (const float*)d_in[0];
    const float* deltas = (const float*)d_in[1];
    const float* dbox   = (const float*)d_in[2];
    float* out = (float*)d_out;

    static int smem_set = 0;
    if (!smem_set){
        cudaFuncSetAttribute(k2_select_nms, cudaFuncAttributeMaxDynamicSharedMemorySize,
                             NPAD*sizeof(u32));
        smem_set = 1;
    }

    int total = NB*NA;
    k1_softmax<<<(total + 255)/256, 256>>>(logits);
    k2_select_nms<<<NB*NFG, K2T, NPAD*sizeof(u32)>>>(deltas, dbox);
    k3_merge<<<NB, 512>>>(out);
}

// round 4
// speedup vs baseline: 1.5486x; 1.5486x over previous
#include <cuda_runtime.h>
#include <cstdint>

typedef unsigned int u32;
typedef unsigned long long u64;

#define NB 32
#define NA 49056
#define NFG 7
#define TOPK 200
#define DETS 200
#define NMSTHR 0.45f
#define LOWSC 0.01f
#define LPB 0x3C23D70Bu   // bits(0.01f)+1 : v >= LPB  <=>  score > 0.01f

#define K2T 512
#define N4 (NA/4)         // 12264 float4 loads per class slice
#define CAP 4096

// ---------------- scratch ----------------------------------------------------
__device__ float g_fg[(size_t)NB*NFG*NA];     // fg scores, class-major
__device__ float g_ks[NB*NFG*TOPK];           // kept scores (sorted desc)
__device__ int   g_ka[NB*NFG*TOPK];           // kept anchors
__device__ float4 g_kb[NB*NFG*TOPK];          // kept clipped boxes (unoffset)
__device__ int   g_kc[NB*NFG];                // kept counts

// ---------------- K1: softmax ------------------------------------------------
__global__ void k1_softmax(const float* __restrict__ logits)
{
    int idx = blockIdx.x*blockDim.x + threadIdx.x;
    if (idx >= NB*NA) return;
    int b = idx / NA;
    int a = idx - b*NA;

    float4 l0 = ((const float4*)logits)[idx*2+0];
    float4 l1 = ((const float4*)logits)[idx*2+1];
    float e[8] = {l0.x,l0.y,l0.z,l0.w,l1.x,l1.y,l1.z,l1.w};
    float mx = e[0];
#pragma unroll
    for (int i=1;i<8;i++) mx = fmaxf(mx,e[i]);
    float s = 0.f;
#pragma unroll
    for (int i=0;i<8;i++){ e[i] = expf(e[i]-mx); s += e[i]; }
    float inv = 1.0f / s;
#pragma unroll
    for (int c=0;c<7;c++)
        g_fg[((size_t)b*NFG + c)*NA + a] = e[c+1]*inv;
}

// ---------------- K2: sample-pivot top-200 + sort + class NMS ----------------
__global__ __launch_bounds__(K2T) void k2_select_nms(const float* __restrict__ deltas,
                                                     const float* __restrict__ dboxg)
{
    extern __shared__ u64 keys[];             // [CAP] candidate keys (dynamic, 32KB)

    __shared__ u32 ssamp[1024];
    __shared__ int sh_cnt;
    __shared__ u32 cs[TOPK];
    __shared__ int ca[TOPK];
    __shared__ float4 rbox[TOPK];
    __shared__ float sx0[TOPK], sy0[TOPK], sx1[TOPK], sy1[TOPK], sar[TOPK];
    __shared__ u32 M[TOPK*7];
    __shared__ u32 skeep[7];
    __shared__ int warpcnt[8], warpbase[8];

    int bc = blockIdx.x;
    int b  = bc / NFG;
    int c  = bc - b*NFG;
    int tid = threadIdx.x;
    int lane = tid & 31;

    const u32*    scu  = (const u32*)(g_fg) + (size_t)bc*NA;
    const float4* src4 = (const float4*)((const float*)g_fg + (size_t)bc*NA);

    // ---- 1024 strided samples ----
#pragma unroll
    for (int q=0;q<2;q++){
        int j = tid + q*K2T;
        ssamp[j] = scu[(j*NA) >> 10];
    }
    __syncthreads();

    // ---- bitonic ascending sort of samples ----
    for (int kk=2; kk<=1024; kk<<=1){
        for (int j=kk>>1; j>0; j>>=1){
            for (int i=tid; i<1024; i+=K2T){
                int ix = i ^ j;
                if (ix > i){
                    u32 a0=ssamp[i], a1=ssamp[ix];
                    bool up = ((i & kk) == 0);
                    if ((a0 > a1) == up){ ssamp[i]=a1; ssamp[ix]=a0; }
                }
            }
            __syncthreads();
        }
    }
    u32 t1 = ssamp[1013];   // 11th largest
    u32 t2 = ssamp[983];    // 41st largest
    __syncthreads();

    // ---- streaming compaction pass (count + append survivors) ----
    auto do_pass = [&](u32 tb)->int{
        if (tid==0) sh_cnt = 0;
        __syncthreads();
#pragma unroll
        for (int k=0;k<24;k++){
            int i4 = tid + (k<<9);
            if (i4 < N4){
                float4 f = src4[i4];
                int abase = i4 << 2;
                u32 vv[4] = {__float_as_uint(f.x), __float_as_uint(f.y),
                             __float_as_uint(f.z), __float_as_uint(f.w)};
#pragma unroll
                for (int t=0;t<4;t++){
                    if (vv[t] >= tb){
                        int p = atomicAdd(&sh_cnt, 1);
                        if (p < CAP)
                            keys[p] = ~(((u64)vv[t] << 32)
                                      | (u64)(0xFFFFFFFFu - (u32)(abase+t)));
                    }
                }
            }
        }
        __syncthreads();
        int r = sh_cnt;
        __syncthreads();
        return r;
    };

    u32 tb = (t1 > LPB) ? t1 : LPB;
    int n = do_pass(tb);
    if (n < TOPK && tb > LPB){
        tb = (t2 > LPB) ? t2 : LPB;
        n = do_pass(tb);
        if (n < TOPK && tb > LPB){
            tb = LPB;
            n = do_pass(tb);
        }
    }
    if (n > CAP) n = CAP;

    // ---- bitonic sort survivors (inverted keys ascending = score desc, anchor asc)
    int np2 = 256;
    while (np2 < n) np2 <<= 1;
    for (int i = tid; i < np2; i += K2T) if (i >= n) keys[i] = ~0ull;
    __syncthreads();
    for (int kk=2; kk<=np2; kk<<=1){
        for (int j=kk>>1; j>0; j>>=1){
            for (int i=tid; i<np2; i+=K2T){
                int ix = i ^ j;
                if (ix > i){
                    u64 a0=keys[i], a1=keys[ix];
                    bool up = ((i & kk) == 0);
                    if ((a0 > a1) == up){ keys[i]=a1; keys[ix]=a0; }
                }
            }
            __syncthreads();
        }
    }

    int m = (n < TOPK) ? n : TOPK;   // all survivors have score > LOW_SCORE
    if (tid < m){
        u64 kk = ~keys[tid];
        cs[tid] = (u32)(kk >> 32);
        ca[tid] = (int)(0xFFFFFFFFu - (u32)kk);
    }
    __syncthreads();

    // ---- decode boxes for the m candidates + class-offset + area ----
    float off = 4.0f * (float)(c + 1);
    for (int i = tid; i < m; i += K2T){
        int a = ca[i];
        float4 d  = ((const float4*)deltas)[(size_t)b*NA + a];
        float4 db = ((const float4*)dboxg)[a];
        float w  = db.z - db.x, h = db.w - db.y;
        float cx = db.x + 0.5f*w, cy = db.y + 0.5f*h;
        float pcx = d.x/10.0f*w + cx;
        float pcy = d.y/10.0f*h + cy;
        float pw  = expf(d.z/5.0f)*w;
        float ph  = expf(d.w/5.0f)*h;
        float4 rb;
        rb.x = fminf(fmaxf(pcx - 0.5f*pw, 0.f), 1.f);
        rb.y = fminf(fmaxf(pcy - 0.5f*ph, 0.f), 1.f);
        rb.z = fminf(fmaxf(pcx + 0.5f*pw, 0.f), 1.f);
        rb.w = fminf(fmaxf(pcy + 0.5f*ph, 0.f), 1.f);
        rbox[i] = rb;
        float x0 = rb.x + off, y0 = rb.y + off;
        float x1 = rb.z + off, y1 = rb.w + off;
        sx0[i]=x0; sy0[i]=y0; sx1[i]=x1; sy1[i]=y1;
        sar[i] = (x1-x0)*(y1-y0);
    }
    for (int i = tid; i < TOPK*7; i += K2T) M[i] = 0u;
    __syncthreads();

    // ---- suppression matrix ----
    int nww = (m + 31) >> 5;
    int ntask = m * nww;
    for (int task = tid; task < ntask; task += K2T){
        int i = task / nww;
        int w = task - i*nww;
        float xi0=sx0[i], yi0=sy0[i], xi1=sx1[i], yi1=sy1[i], ai=sar[i];
        u32 bits = 0;
#pragma unroll
        for (int l=0;l<32;l++){
            int idx = (l + lane) & 31;
            int j = (w<<5) + idx;
            if (j < m && j > i){
                float xl = fmaxf(xi0, sx0[j]);
                float yt = fmaxf(yi0, sy0[j]);
                float xr = fminf(xi1, sx1[j]);
                float yb = fminf(yi1, sy1[j]);
                float inter = fmaxf(xr-xl, 0.f) * fmaxf(yb-yt, 0.f);
                float iou = inter / (ai + sar[j] - inter);
                if (iou > NMSTHR) bits |= (1u << idx);
            }
        }
        M[i*7 + w] = bits;
    }
    __syncthreads();

    // ---- serial greedy walk (thread 0) ----
    if (tid == 0){
        u32 r0=0,r1=0,r2=0,r3=0,r4=0,r5=0,r6=0;
#define NMSW(W, RW) { int lim = m - (W<<5); if (lim > 32) lim = 32; \
        for (int l=0;l<lim;l++){ \
            if (!((RW >> l) & 1u)){ const u32* row = &M[(((W)<<5)+l)*7]; \
                r0|=row[0]; r1|=row[1]; r2|=row[2]; r3|=row[3]; r4|=row[4]; r5|=row[5]; r6|=row[6]; } } }
        if (m >   0) NMSW(0, r0)
        if (m >  32) NMSW(1, r1)
        if (m >  64) NMSW(2, r2)
        if (m >  96) NMSW(3, r3)
        if (m > 128) NMSW(4, r4)
        if (m > 160) NMSW(5, r5)
        if (m > 192) NMSW(6, r6)
#undef NMSW
        skeep[0]=~r0; skeep[1]=~r1; skeep[2]=~r2; skeep[3]=~r3;
        skeep[4]=~r4; skeep[5]=~r5; skeep[6]=~r6;
    }
    __syncthreads();

    // ---- ordered compaction of kept -> global ----
    u32 bal = 0; bool kept = false;
    int w7 = tid >> 5;
    if (tid < 224){
        kept = (tid < m) && ((skeep[w7] >> lane) & 1u);
        bal = __ballot_sync(0xffffffffu, kept);
        if (lane == 0) warpcnt[w7] = __popc(bal);
    }
    __syncthreads();
    if (tid == 0){
        int s = 0;
        for (int w=0; w<7; w++){ warpbase[w] = s; s += warpcnt[w]; }
        g_kc[bc] = s;
    }
    __syncthreads();
    if (tid < 224 && kept){
        int pos = warpbase[w7] + __popc(bal & ((1u << lane) - 1u));
        g_ks[bc*TOPK + pos] = __uint_as_float(cs[tid]);
        g_ka[bc*TOPK + pos] = ca[tid];
        g_kb[bc*TOPK + pos] = rbox[tid];
    }
}

// ---------------- K3: per-batch rank-merge of 7 kept lists -------------------
__global__ __launch_bounds__(512) void k3_merge(float* __restrict__ out)
{
    __shared__ u64 sk[NFG*TOPK];
    __shared__ int scnt[NFG];

    int b = blockIdx.x;
    int tid = threadIdx.x;

    for (int d = tid; d < DETS; d += 512){
        int base = b*DETS + d;
        out[base*4+0]=0.f; out[base*4+1]=0.f; out[base*4+2]=0.f; out[base*4+3]=0.f;
        out[NB*DETS*4 + base] = 0.f;
        out[NB*DETS*5 + base] = 0.f;
    }
    if (tid < NFG) scnt[tid] = g_kc[b*NFG + tid];
    __syncthreads();

    for (int idx = tid; idx < NFG*TOPK; idx += 512){
        int c = idx / TOPK;
        int p = idx - c*TOPK;
        u64 key = 0;
        if (p < scnt[c]){
            float s = g_ks[(b*NFG + c)*TOPK + p];
            int   a = g_ka[(b*NFG + c)*TOPK + p];
            key = ((u64)__float_as_uint(s) << 32)
                | ((u64)(u32)((7 - c) << 16))
                | (u64)(u32)(0xFFFF - a);
        }
        sk[idx] = key;
    }
    __syncthreads();

    for (int idx = tid; idx < NFG*TOPK; idx += 512){
        int c = idx / TOPK;
        int p = idx - c*TOPK;
        if (p < scnt[c]){
            u64 K = sk[idx];
            int r = p;
#pragma unroll
            for (int c2=0; c2<NFG; c2++){
                if (c2 == c) continue;
                const u64* L = sk + c2*TOPK;
                int blo = 0, bhi = scnt[c2];
                while (blo < bhi){
                    int mid = (blo + bhi) >> 1;
                    if (L[mid] > K) blo = mid + 1; else bhi = mid;
                }
                r += blo;
            }
            if (r < DETS){
                float4 bb = g_kb[(b*NFG + c)*TOPK + p];
                float  s  = __uint_as_float((u32)(K >> 32));
                int base = b*DETS + r;
                out[base*4+0]=bb.x; out[base*4+1]=bb.y;
                out[base*4+2]=bb.z; out[base*4+3]=bb.w;
                out[NB*DETS*4 + base] = s;
                out[NB*DETS*5 + base] = (float)(c + 1);
            }
        }
    }
}

// ---------------- launch ----------------------------------------------------
extern "C" void kernel_launch(void* const* d_in, const int* in_sizes, int n_in,
                              void* d_out, int out_size)
{
    const float* logits = (const float*)d_in[0];
    const float* deltas = (const float*)d_in[1];
    const float* dbox   = (const float*)d_in[2];
    float* out = (float*)d_out;

    static int smem_set = 0;
    if (!smem_set){
        cudaFuncSetAttribute(k2_select_nms, cudaFuncAttributeMaxDynamicSharedMemorySize,
                             CAP*sizeof(u64));
        smem_set = 1;
    }

    int total = NB*NA;
    k1_softmax<<<(total + 255)/256, 256>>>(logits);
    k2_select_nms<<<NB*NFG, K2T, CAP*sizeof(u64)>>>(deltas, dbox);
    k3_merge<<<NB, 512>>>(out);
}